// round 16
// baseline (speedup 1.0000x reference)
#include <cuda_runtime.h>
#include <cuda_fp16.h>
#include <math.h>
#include <float.h>
#include <stdint.h>

#define SEQ    1024
#define DMODEL 1024
#define NHEAD  16
#define DHEAD  64
#define NBATCH 2
#define POS2   512
#define GTOT   (NBATCH * SEQ)

// ---------------- scratch ----------------------------------------------------
__device__ __half g_Hh[NBATCH * SEQ * DMODEL];
__device__ __half g_Rh[POS2 * DMODEL];
__device__ __half g_WT[3 * DMODEL * DMODEL];
__device__ __half g_Q[NBATCH * SEQ * DMODEL];            // pre-scaled by log2e/scale
__device__ __half g_K[NBATCH * SEQ * DMODEL];
__device__ __half g_VT[NBATCH * DMODEL * SEQ];           // [b*1024+ch][s]
__device__ __half g_PQ[POS2 * DMODEL];                   // pre-scaled by log2e/scale
__device__ __half g_PK[POS2 * DMODEL];
__device__ __half g_c2pT[NHEAD * POS2 * GTOT];           // [h][bucket][g]
__device__ __half g_p2cT[NHEAD * POS2 * GTOT];           // [h][bucket][g]
__device__ ushort2 g_idx2s[2047];
__device__ unsigned g_pmask[NBATCH * SEQ * (SEQ / 32)];

#define INV_SCALE 0.07216878364870323f
#define LOG2E     1.4426950408889634f

// ---------------- helpers ----------------------------------------------------
__device__ __forceinline__ void mma_f16(float c[4], const uint32_t a[4], const uint32_t b[2]) {
    asm volatile(
        "mma.sync.aligned.m16n8k16.row.col.f32.f16.f16.f32 "
        "{%0,%1,%2,%3}, {%4,%5,%6,%7}, {%8,%9}, {%0,%1,%2,%3};"
        : "+f"(c[0]), "+f"(c[1]), "+f"(c[2]), "+f"(c[3])
        : "r"(a[0]), "r"(a[1]), "r"(a[2]), "r"(a[3]), "r"(b[0]), "r"(b[1]));
}
__device__ __forceinline__ uint32_t packh2(float lo, float hi) {
    __half2 h = __floats2half2_rn(lo, hi);
    return *(uint32_t*)&h;
}
__device__ __forceinline__ float fexp2(float x) {
    float y;
    asm("ex2.approx.ftz.f32 %0, %1;" : "=f"(y) : "f"(x));
    return y;
}
__device__ __forceinline__ void cp16(uint32_t dst, const void* src) {
    asm volatile("cp.async.ca.shared.global [%0], [%1], 16;" :: "r"(dst), "l"(src));
}

__device__ __forceinline__ int log_bucket(int rel) {
    const int mid = 128;
    float absp;
    if (rel < mid && rel > -mid) absp = (float)(mid - 1);
    else absp = fabsf((float)rel);
    if (absp <= (float)mid) return rel;
    float lp = ceilf(logf(absp / 128.0f) / 1.3843393291f * 127.0f) + 128.0f;
    float sgn = (rel > 0) ? 1.0f : ((rel < 0) ? -1.0f : 0.0f);
    return (int)(lp * sgn);
}

// ================= fused pre-pass kernel =====================================
#define PREP_PACK   8192
#define PREP_CONVH  (PREP_PACK + 2048)
#define PREP_CONVR  (PREP_CONVH + 512)
#define PREP_TRANS  (PREP_CONVR + 3072)
#define PREP_TOTAL  (PREP_TRANS + 8)

__global__ __launch_bounds__(256) void prep_all(
    const int* __restrict__ mask, const float* __restrict__ hidden,
    const float* __restrict__ rel,
    const float* __restrict__ W0, const float* __restrict__ W1,
    const float* __restrict__ W2) {
    int blk = blockIdx.x;
    int tid = threadIdx.x;

    if (blk < PREP_PACK) {
        int idx = blk * 256 + tid;
        int v = mask[idx];
        unsigned bal = __ballot_sync(0xffffffffu, v != 0);
        if ((tid & 31) == 0) g_pmask[idx >> 5] = bal;
    } else if (blk < PREP_CONVH) {
        int i = (blk - PREP_PACK) * 256 + tid;
        float4 v = ((const float4*)hidden)[i];
        ((__half2*)g_Hh)[2 * i]     = __floats2half2_rn(v.x, v.y);
        ((__half2*)g_Hh)[2 * i + 1] = __floats2half2_rn(v.z, v.w);
    } else if (blk < PREP_CONVR) {
        int i = (blk - PREP_CONVH) * 256 + tid;
        float4 v = ((const float4*)rel)[i];
        ((__half2*)g_Rh)[2 * i]     = __floats2half2_rn(v.x, v.y);
        ((__half2*)g_Rh)[2 * i + 1] = __floats2half2_rn(v.z, v.w);
    } else if (blk < PREP_TRANS) {
        __shared__ float t[32][33];
        int r = blk - PREP_CONVR;
        int bx = r & 31, by = (r >> 5) & 31, bz = r >> 10;
        const float* W = (bz == 0) ? W0 : (bz == 1) ? W1 : W2;
        __half* D = g_WT + (size_t)bz * DMODEL * DMODEL;
        int tx = tid & 31, ty = tid >> 5;
        int x = bx * 32 + tx;
        int y0 = by * 32 + ty;
        #pragma unroll
        for (int i = 0; i < 32; i += 8)
            t[ty + i][tx] = W[(size_t)(y0 + i) * 1024 + x];
        __syncthreads();
        int nx = by * 32 + tx;
        int ny = bx * 32 + ty;
        #pragma unroll
        for (int i = 0; i < 32; i += 8)
            D[(size_t)(ny + i) * 1024 + nx] = __float2half(t[tx][ty + i]);
    } else {
        int t = (blk - PREP_TRANS) * 256 + tid;
        if (t < 2047) {
            int delta = t - 1023;
            int bC = log_bucket(delta);
            int bP = log_bucket(-delta);
            ushort2 v;
            v.x = (unsigned short)min(max(bC + 256, 0), 511);
            v.y = (unsigned short)min(max(-bP + 256, 0), 511);
            g_idx2s[t] = v;
        }
    }
}

// ================= FP16 GEMM: projections (cp.async double-buffered) =========
#define PAS 40
#define PBUF (128 * PAS)

__global__ __launch_bounds__(256) void gemm_proj_f16(
    const float* __restrict__ bq, const float* __restrict__ bk, const float* __restrict__ bv) {

    int z = blockIdx.z;
    int y = blockIdx.y;
    const __half* A;
    __half* Ch = nullptr;
    bool isV = false;
    int m0;
    if (y < 16) {
        A = g_Hh; m0 = y * 128;
        if (z == 0) Ch = g_Q; else if (z == 1) Ch = g_K; else isV = true;
    } else {
        if (z == 2) return;
        A = g_Rh; m0 = (y - 16) * 128;
        Ch = (z == 0) ? g_PQ : g_PK;
    }
    const __half* WT = g_WT + (size_t)z * DMODEL * DMODEL;
    const float* bias = (z == 0) ? bq : (z == 1) ? bk : bv;
    float outscale = (z == 0) ? (INV_SCALE * LOG2E) : 1.0f;

    extern __shared__ __half smh[];
    __half* As = smh;
    __half* Bs = smh + 2 * PBUF;
    uint32_t as_u32 = (uint32_t)__cvta_generic_to_shared(As);
    uint32_t bs_u32 = (uint32_t)__cvta_generic_to_shared(Bs);

    int tid = threadIdx.x;
    int lane = tid & 31, wid = tid >> 5;
    int qd = lane & 3, g = lane >> 2;
    int wm = (wid >> 2) * 64, wn = (wid & 3) * 32;
    int n0 = blockIdx.x * 128;

    float acc[16][4];
    #pragma unroll
    for (int t = 0; t < 16; t++)
        #pragma unroll
        for (int j = 0; j < 4; j++) acc[t][j] = 0.0f;

    #pragma unroll
    for (int i = 0; i < 2; i++) {
        int idx = tid + i * 256;
        int row = idx >> 2, c8 = (idx & 3) * 8;
        cp16(as_u32 + (row * PAS + c8) * 2, &A[(size_t)(m0 + row) * 1024 + c8]);
        cp16(bs_u32 + (row * PAS + c8) * 2, &WT[(size_t)(n0 + row) * 1024 + c8]);
    }
    asm volatile("cp.async.commit_group;");
    asm volatile("cp.async.wait_group 0;");
    __syncthreads();

    int buf = 0;
    for (int c = 0; c < 32; c++) {
        if (c + 1 < 32) {
            int kk = (c + 1) * 32;
            int nb = buf ^ 1;
            #pragma unroll
            for (int i = 0; i < 2; i++) {
                int idx = tid + i * 256;
                int row = idx >> 2, c8 = (idx & 3) * 8;
                cp16(as_u32 + (nb * PBUF + row * PAS + c8) * 2,
                     &A[(size_t)(m0 + row) * 1024 + kk + c8]);
                cp16(bs_u32 + (nb * PBUF + row * PAS + c8) * 2,
                     &WT[(size_t)(n0 + row) * 1024 + kk + c8]);
            }
            asm volatile("cp.async.commit_group;");
        }

        const __half* Ab = &As[buf * PBUF];
        const __half* Bb = &Bs[buf * PBUF];
        #pragma unroll
        for (int ks = 0; ks < 2; ks++) {
            int kb = ks * 16 + 2 * qd;
            uint32_t af[4][4], bf[4][2];
            #pragma unroll
            for (int i = 0; i < 4; i++) {
                int r = wm + i * 16 + g;
                af[i][0] = *(const uint32_t*)&Ab[r * PAS + kb];
                af[i][1] = *(const uint32_t*)&Ab[(r + 8) * PAS + kb];
                af[i][2] = *(const uint32_t*)&Ab[r * PAS + kb + 8];
                af[i][3] = *(const uint32_t*)&Ab[(r + 8) * PAS + kb + 8];
            }
            #pragma unroll
            for (int j = 0; j < 4; j++) {
                int n = wn + j * 8 + g;
                bf[j][0] = *(const uint32_t*)&Bb[n * PAS + kb];
                bf[j][1] = *(const uint32_t*)&Bb[n * PAS + kb + 8];
            }
            #pragma unroll
            for (int i = 0; i < 4; i++)
                #pragma unroll
                for (int j = 0; j < 4; j++)
                    mma_f16(acc[i * 4 + j], af[i], bf[j]);
        }

        asm volatile("cp.async.wait_group 0;");
        __syncthreads();
        buf ^= 1;
    }

    #pragma unroll
    for (int i = 0; i < 4; i++) {
        #pragma unroll
        for (int j = 0; j < 4; j++) {
            int r = m0 + wm + i * 16 + g;
            int c = n0 + wn + j * 8 + 2 * qd;
            float bx = bias[c], by = bias[c + 1];
            float v00 = (acc[i * 4 + j][0] + bx) * outscale, v01 = (acc[i * 4 + j][1] + by) * outscale;
            float v10 = (acc[i * 4 + j][2] + bx) * outscale, v11 = (acc[i * 4 + j][3] + by) * outscale;
            if (!isV) {
                *(__half2*)&Ch[(size_t)r * 1024 + c] = __floats2half2_rn(v00, v01);
                *(__half2*)&Ch[(size_t)(r + 8) * 1024 + c] = __floats2half2_rn(v10, v11);
            } else {
                int bb = r >> 10, s = r & 1023;
                size_t base = ((size_t)(bb * 1024 + c)) * 1024;
                g_VT[base + s] = __float2half(v00);
                g_VT[base + 1024 + s] = __float2half(v01);
                g_VT[base + s + 8] = __float2half(v10);
                g_VT[base + 1024 + s + 8] = __float2half(v11);
            }
        }
    }
}

// ============ FP16 positional GEMMs: BOTH outputs bucket-major ===============
#define ABH 72

__global__ __launch_bounds__(256) void gemm_abT_f16() {
    int z = blockIdx.z;
    int h = z & 15;
    bool c2p = (z < 16);
    const __half* Ap = c2p ? g_PK : g_PQ;
    const __half* Bp = c2p ? g_Q  : g_K;
    __half* Cp = c2p ? g_c2pT : g_p2cT;
    int r0 = blockIdx.x * 128;
    int n0 = blockIdx.y * 128;

    extern __shared__ __half smh[];
    __half* As = smh;
    __half* Bs = smh + 128 * ABH;

    int tid = threadIdx.x;
    int lane = tid & 31, wid = tid >> 5;
    int qd = lane & 3, g = lane >> 2;
    int wm = (wid >> 1) * 32, wn = (wid & 1) * 64;

    #pragma unroll
    for (int it = 0; it < 8; it++) {
        int idx = tid + it * 256;
        int row = idx >> 4, q = (idx & 15) * 4;
        *(uint2*)&As[row * ABH + q] = *(const uint2*)&Ap[(size_t)(r0 + row) * 1024 + h * 64 + q];
        *(uint2*)&Bs[row * ABH + q] = *(const uint2*)&Bp[(size_t)(n0 + row) * 1024 + h * 64 + q];
    }
    __syncthreads();

    float acc[16][4];
    #pragma unroll
    for (int t = 0; t < 16; t++)
        #pragma unroll
        for (int j = 0; j < 4; j++) acc[t][j] = 0.0f;

    #pragma unroll
    for (int s = 0; s < 4; s++) {
        int kb = s * 16 + 2 * qd;
        uint32_t af[2][4], bf[8][2];
        #pragma unroll
        for (int i = 0; i < 2; i++) {
            int r = wm + i * 16 + g;
            af[i][0] = *(uint32_t*)&As[r * ABH + kb];
            af[i][1] = *(uint32_t*)&As[(r + 8) * ABH + kb];
            af[i][2] = *(uint32_t*)&As[r * ABH + kb + 8];
            af[i][3] = *(uint32_t*)&As[(r + 8) * ABH + kb + 8];
        }
        #pragma unroll
        for (int j = 0; j < 8; j++) {
            int p = wn + j * 8 + g;
            bf[j][0] = *(uint32_t*)&Bs[p * ABH + kb];
            bf[j][1] = *(uint32_t*)&Bs[p * ABH + kb + 8];
        }
        #pragma unroll
        for (int i = 0; i < 2; i++)
            #pragma unroll
            for (int j = 0; j < 8; j++)
                mma_f16(acc[i * 8 + j], af[i], bf[j]);
    }

    #pragma unroll
    for (int i = 0; i < 2; i++) {
        #pragma unroll
        for (int j = 0; j < 8; j++) {
            int r = r0 + wm + i * 16 + g;
            int c = n0 + wn + j * 8 + 2 * qd;
            *(__half2*)&Cp[((size_t)h * POS2 + r) * GTOT + c] =
                __floats2half2_rn(acc[i * 8 + j][0], acc[i * 8 + j][1]);
            *(__half2*)&Cp[((size_t)h * POS2 + r + 8) * GTOT + c] =
                __floats2half2_rn(acc[i * 8 + j][2], acc[i * 8 + j][3]);
        }
    }
}

// ================= FP16 flash attention (bias pipelined via smem scratch) ====
#define AQH 72
#define KVB (64 * AQH)

__global__ __launch_bounds__(256, 2) void attn_tc_kernel(float* __restrict__ out) {
    extern __shared__ __half smh[];
    __half* Qs = smh;               // [128][72]
    __half* Kb = Qs + 128 * AQH;    // [2][64][72]
    __half* Vb = Kb + 2 * KVB;      // [2][64][72]
    ushort2* idxs = (ushort2*)(Vb + 2 * KVB);        // [1152]
    uint32_t* biasb = (uint32_t*)(idxs + 1152);      // [2][16*256] packed half2

    uint32_t smem_u32 = (uint32_t)__cvta_generic_to_shared(smh);
    uint32_t kb_u32 = smem_u32 + 128 * AQH * 2;
    uint32_t vb_u32 = kb_u32 + 2 * KVB * 2;

    int tid = threadIdx.x;
    int lane = tid & 31, wid = tid >> 5;
    int qd = lane & 3, g = lane >> 2;
    int bh = blockIdx.y;
    int b = bh >> 4, h = bh & 15;
    int q0 = blockIdx.x * 128;

    {
        #pragma unroll
        for (int it = 0; it < 2; it++) {
            int idx = tid + it * 256;
            int row = idx >> 3, c8 = (idx & 7) * 8;
            cp16(kb_u32 + (row * AQH + c8) * 2,
                 &g_K[(size_t)(b * SEQ + row) * 1024 + h * 64 + c8]);
            cp16(vb_u32 + (row * AQH + c8) * 2,
                 &g_VT[((size_t)(b * 1024 + h * 64 + row)) * 1024 + c8]);
        }
        asm volatile("cp.async.commit_group;");
    }
    #pragma unroll
    for (int it = 0; it < 8; it++) {
        int idx = tid + it * 256;
        int row = idx >> 4, q = (idx & 15) * 4;
        *(uint2*)&Qs[row * AQH + q] = *(const uint2*)&g_Q[(size_t)(b * SEQ + q0 + row) * 1024 + h * 64 + q];
    }
    for (int t = tid; t < 1151; t += 256) idxs[t] = g_idx2s[q0 + t];

    int r0l = wid * 16 + g;
    int row0 = q0 + r0l, row1 = row0 + 8;
    int brow0 = b * SEQ + row0;
    const __half* c2pb = &g_c2pT[(size_t)h * POS2 * GTOT];
    const __half* p2cb = &g_p2cT[(size_t)h * POS2 * GTOT + b * SEQ];
    const unsigned* pm0 = &g_pmask[(size_t)(b * SEQ + row0) * 32];
    const unsigned* pm1 = &g_pmask[(size_t)(b * SEQ + row1) * 32];

    float m_run0 = -FLT_MAX, m_run1 = -FLT_MAX, l_run0 = 0.0f, l_run1 = 0.0f;
    float O[8][4];
    #pragma unroll
    for (int f = 0; f < 8; f++)
        #pragma unroll
        for (int j = 0; j < 4; j++) O[f][j] = 0.0f;

    // idx table needed before first bias prefetch
    __syncthreads();

    // prefetch bias for tile 0 into buffer 0 (thread-private slots, no sync)
    #pragma unroll
    for (int s = 0; s < 16; s++) {
        int nf = s >> 1, j = s & 1;
        int kl = nf * 8 + 2 * qd + j;
        int kg = kl;                       // k0 = 0
        int li = r0l - kg + 1023;
        ushort2 i0 = idxs[li];
        ushort2 i1 = idxs[li + 8];
        float b0 = __half2float(__ldg(&c2pb[(size_t)i0.x * GTOT + brow0]))
                 + __half2float(__ldg(&p2cb[(size_t)i0.y * GTOT + kg]));
        float b1 = __half2float(__ldg(&c2pb[(size_t)i1.x * GTOT + brow0 + 8]))
                 + __half2float(__ldg(&p2cb[(size_t)i1.y * GTOT + kg]));
        biasb[s * 256 + tid] = packh2(b0, b1);
    }

    asm volatile("cp.async.wait_group 0;");
    __syncthreads();

    int buf = 0;
    for (int k0 = 0; k0 < SEQ; k0 += 64) {
        int nb = buf ^ 1;
        if (k0 + 64 < SEQ) {
            int nk = k0 + 64;
            #pragma unroll
            for (int it = 0; it < 2; it++) {
                int idx = tid + it * 256;
                int row = idx >> 3, c8 = (idx & 7) * 8;
                cp16(kb_u32 + (nb * KVB + row * AQH + c8) * 2,
                     &g_K[(size_t)(b * SEQ + nk + row) * 1024 + h * 64 + c8]);
                cp16(vb_u32 + (nb * KVB + row * AQH + c8) * 2,
                     &g_VT[((size_t)(b * 1024 + h * 64 + row)) * 1024 + nk + c8]);
            }
            asm volatile("cp.async.commit_group;");

            // prefetch NEXT tile's bias into the spare buffer (independent of
            // everything below; ptxas overlaps the LDG latency with S/softmax/PV)
            #pragma unroll
            for (int s = 0; s < 16; s++) {
                int nf = s >> 1, j = s & 1;
                int kl = nf * 8 + 2 * qd + j;
                int kg = nk + kl;
                int li = r0l - kg + 1023;
                ushort2 i0 = idxs[li];
                ushort2 i1 = idxs[li + 8];
                float b0 = __half2float(__ldg(&c2pb[(size_t)i0.x * GTOT + brow0]))
                         + __half2float(__ldg(&p2cb[(size_t)i0.y * GTOT + kg]));
                float b1 = __half2float(__ldg(&c2pb[(size_t)i1.x * GTOT + brow0 + 8]))
                         + __half2float(__ldg(&p2cb[(size_t)i1.y * GTOT + kg]));
                biasb[nb * 4096 + s * 256 + tid] = packh2(b0, b1);
            }
        }

        const __half* Ks = Kb + buf * KVB;
        const __half* Vt = Vb + buf * KVB;
        const uint32_t* bcur = biasb + buf * 4096;

        // ---- S = Q K^T (pre-scaled, log2 units)
        float sa[8][4];
        #pragma unroll
        for (int f = 0; f < 8; f++)
            #pragma unroll
            for (int j = 0; j < 4; j++) sa[f][j] = 0.0f;

        #pragma unroll
        for (int s = 0; s < 4; s++) {
            int kb = s * 16 + 2 * qd;
            uint32_t a[4];
            a[0] = *(uint32_t*)&Qs[r0l * AQH + kb];
            a[1] = *(uint32_t*)&Qs[(r0l + 8) * AQH + kb];
            a[2] = *(uint32_t*)&Qs[r0l * AQH + kb + 8];
            a[3] = *(uint32_t*)&Qs[(r0l + 8) * AQH + kb + 8];
            #pragma unroll
            for (int nf = 0; nf < 8; nf++) {
                int n = nf * 8 + g;
                uint32_t bfr[2];
                bfr[0] = *(uint32_t*)&Ks[n * AQH + kb];
                bfr[1] = *(uint32_t*)&Ks[n * AQH + kb + 8];
                mma_f16(sa[nf], a, bfr);
            }
        }

        unsigned m0a = pm0[k0 >> 5], m0b = pm0[(k0 >> 5) + 1];
        unsigned m1a = pm1[k0 >> 5], m1b = pm1[(k0 >> 5) + 1];

        // ---- bias (from smem scratch) + mask
        float s0max = -FLT_MAX, s1max = -FLT_MAX;
        #pragma unroll
        for (int nf = 0; nf < 8; nf++) {
            #pragma unroll
            for (int j = 0; j < 2; j++) {
                int kl = nf * 8 + 2 * qd + j;
                uint32_t pk = bcur[(nf * 2 + j) * 256 + tid];
                float2 bb = __half22float2(*(__half2*)&pk);
                float v0 = sa[nf][j] + bb.x;
                float v1 = sa[nf][j + 2] + bb.y;
                unsigned w0 = (kl & 32) ? m0b : m0a;
                unsigned w1 = (kl & 32) ? m1b : m1a;
                v0 = ((w0 >> (kl & 31)) & 1u) ? v0 : -FLT_MAX;
                v1 = ((w1 >> (kl & 31)) & 1u) ? v1 : -FLT_MAX;
                sa[nf][j] = v0; sa[nf][j + 2] = v1;
                s0max = fmaxf(s0max, v0); s1max = fmaxf(s1max, v1);
            }
        }

        // ---- online softmax (base-2)
        s0max = fmaxf(s0max, __shfl_xor_sync(0xffffffffu, s0max, 1));
        s0max = fmaxf(s0max, __shfl_xor_sync(0xffffffffu, s0max, 2));
        s1max = fmaxf(s1max, __shfl_xor_sync(0xffffffffu, s1max, 1));
        s1max = fmaxf(s1max, __shfl_xor_sync(0xffffffffu, s1max, 2));
        float m0n = fmaxf(m_run0, s0max), m1n = fmaxf(m_run1, s1max);
        float a0 = fexp2(m_run0 - m0n), a1 = fexp2(m_run1 - m1n);
        float psum0 = 0.0f, psum1 = 0.0f;
        #pragma unroll
        for (int nf = 0; nf < 8; nf++) {
            sa[nf][0] = fexp2(sa[nf][0] - m0n);
            sa[nf][1] = fexp2(sa[nf][1] - m0n);
            sa[nf][2] = fexp2(sa[nf][2] - m1n);
            sa[nf][3] = fexp2(sa[nf][3] - m1n);
            psum0 += sa[nf][0] + sa[nf][1];
            psum1 += sa[nf][2] + sa[nf][3];
        }
        psum0 += __shfl_xor_sync(0xffffffffu, psum0, 1);
        psum0 += __shfl_xor_sync(0xffffffffu, psum0, 2);
        psum1 += __shfl_xor_sync(0xffffffffu, psum1, 1);
        psum1 += __shfl_xor_sync(0xffffffffu, psum1, 2);
        l_run0 = l_run0 * a0 + psum0;
        l_run1 = l_run1 * a1 + psum1;
        m_run0 = m0n; m_run1 = m1n;
        #pragma unroll
        for (int f = 0; f < 8; f++) {
            O[f][0] *= a0; O[f][1] *= a0; O[f][2] *= a1; O[f][3] *= a1;
        }

        // ---- O += P V (fp16 C->A fragment identity)
        #pragma unroll
        for (int s = 0; s < 4; s++) {
            uint32_t a[4];
            a[0] = packh2(sa[2 * s][0],     sa[2 * s][1]);
            a[1] = packh2(sa[2 * s][2],     sa[2 * s][3]);
            a[2] = packh2(sa[2 * s + 1][0], sa[2 * s + 1][1]);
            a[3] = packh2(sa[2 * s + 1][2], sa[2 * s + 1][3]);
            int kb = s * 16 + 2 * qd;
            #pragma unroll
            for (int nf = 0; nf < 8; nf++) {
                int n = nf * 8 + g;
                uint32_t bfr[2];
                bfr[0] = *(uint32_t*)&Vt[n * AQH + kb];
                bfr[1] = *(uint32_t*)&Vt[n * AQH + kb + 8];
                mma_f16(O[nf], a, bfr);
            }
        }

        asm volatile("cp.async.wait_group 0;");
        __syncthreads();
        buf ^= 1;
    }

    float invl0 = (m_run0 == -FLT_MAX) ? 0.0f : (1.0f / l_run0);
    float invl1 = (m_run1 == -FLT_MAX) ? 0.0f : (1.0f / l_run1);
    #pragma unroll
    for (int nf = 0; nf < 8; nf++) {
        int d = nf * 8 + 2 * qd;
        float2 o0 = {O[nf][0] * invl0, O[nf][1] * invl0};
        *(float2*)&out[(size_t)(b * SEQ + row0) * 1024 + h * 64 + d] = o0;
        float2 o1 = {O[nf][2] * invl1, O[nf][3] * invl1};
        *(float2*)&out[(size_t)(b * SEQ + row1) * 1024 + h * 64 + d] = o1;
    }
}

// ---------------- launch ----------------------------------------------------
extern "C" void kernel_launch(void* const* d_in, const int* in_sizes, int n_in,
                              void* d_out, int out_size) {
    const float* hidden = (const float*)d_in[0];
    const int*   mask   = (const int*)d_in[1];
    const float* rel    = (const float*)d_in[2];
    const float* Wq     = (const float*)d_in[3];
    const float* bq     = (const float*)d_in[4];
    const float* Wk     = (const float*)d_in[5];
    const float* bk     = (const float*)d_in[6];
    const float* Wv     = (const float*)d_in[7];
    const float* bv     = (const float*)d_in[8];
    float* out = (float*)d_out;

    prep_all<<<PREP_TOTAL, 256>>>(mask, hidden, rel, Wq, Wk, Wv);

    int smem_proj = 4 * PBUF * (int)sizeof(__half);
    cudaFuncSetAttribute(gemm_proj_f16, cudaFuncAttributeMaxDynamicSharedMemorySize, smem_proj);
    gemm_proj_f16<<<dim3(8, 20, 3), 256, smem_proj>>>(bq, bk, bv);

    int smem_abt = (2 * 128 * ABH) * (int)sizeof(__half);
    cudaFuncSetAttribute(gemm_abT_f16, cudaFuncAttributeMaxDynamicSharedMemorySize, smem_abt);
    gemm_abT_f16<<<dim3(POS2 / 128, GTOT / 128, 32), 256, smem_abt>>>();

    int smem_attn = (128 * AQH + 4 * KVB) * (int)sizeof(__half)
                  + 1152 * (int)sizeof(ushort2)
                  + 2 * 4096 * (int)sizeof(uint32_t);
    cudaFuncSetAttribute(attn_tc_kernel, cudaFuncAttributeMaxDynamicSharedMemorySize, smem_attn);
    attn_tc_kernel<<<dim3(SEQ / 128, NBATCH * NHEAD), 256, smem_attn>>>(out);
}

// round 17
// speedup vs baseline: 1.1220x; 1.1220x over previous
#include <cuda_runtime.h>
#include <cuda_fp16.h>
#include <math.h>
#include <float.h>
#include <stdint.h>

#define SEQ    1024
#define DMODEL 1024
#define NHEAD  16
#define DHEAD  64
#define NBATCH 2
#define POS2   512
#define GTOT   (NBATCH * SEQ)

// ---------------- scratch ----------------------------------------------------
__device__ __half g_Hh[NBATCH * SEQ * DMODEL];
__device__ __half g_Rh[POS2 * DMODEL];
__device__ __half g_WT[3 * DMODEL * DMODEL];
__device__ __half g_Q[NBATCH * SEQ * DMODEL];            // pre-scaled by log2e/scale
__device__ __half g_K[NBATCH * SEQ * DMODEL];
__device__ __half g_VT[NBATCH * DMODEL * SEQ];           // [b*1024+ch][s]
__device__ __half g_PQ[POS2 * DMODEL];                   // pre-scaled by log2e/scale
__device__ __half g_PK[POS2 * DMODEL];
__device__ __half g_c2pT[NHEAD * POS2 * GTOT];           // [h][bucket][g]
__device__ __half g_p2cT[NHEAD * POS2 * GTOT];           // [h][bucket][g]
__device__ ushort2 g_idx2s[2047];
__device__ unsigned g_pmask[NBATCH * SEQ * (SEQ / 32)];

#define INV_SCALE 0.07216878364870323f
#define LOG2E     1.4426950408889634f

// ---------------- helpers ----------------------------------------------------
__device__ __forceinline__ void mma_f16(float c[4], const uint32_t a[4], const uint32_t b[2]) {
    asm volatile(
        "mma.sync.aligned.m16n8k16.row.col.f32.f16.f16.f32 "
        "{%0,%1,%2,%3}, {%4,%5,%6,%7}, {%8,%9}, {%0,%1,%2,%3};"
        : "+f"(c[0]), "+f"(c[1]), "+f"(c[2]), "+f"(c[3])
        : "r"(a[0]), "r"(a[1]), "r"(a[2]), "r"(a[3]), "r"(b[0]), "r"(b[1]));
}
__device__ __forceinline__ uint32_t packh2(float lo, float hi) {
    __half2 h = __floats2half2_rn(lo, hi);
    return *(uint32_t*)&h;
}
__device__ __forceinline__ float fexp2(float x) {
    float y;
    asm("ex2.approx.ftz.f32 %0, %1;" : "=f"(y) : "f"(x));
    return y;
}
__device__ __forceinline__ void cp16(uint32_t dst, const void* src) {
    asm volatile("cp.async.ca.shared.global [%0], [%1], 16;" :: "r"(dst), "l"(src));
}

__device__ __forceinline__ int log_bucket(int rel) {
    const int mid = 128;
    float absp;
    if (rel < mid && rel > -mid) absp = (float)(mid - 1);
    else absp = fabsf((float)rel);
    if (absp <= (float)mid) return rel;
    float lp = ceilf(logf(absp / 128.0f) / 1.3843393291f * 127.0f) + 128.0f;
    float sgn = (rel > 0) ? 1.0f : ((rel < 0) ? -1.0f : 0.0f);
    return (int)(lp * sgn);
}

// ================= fused pre-pass kernel =====================================
// Block ranges: [0,2048) pack_mask(int4) | [2048,4096) conv hidden |
// [4096,4608) conv rel | [4608,7680) transpose W | [7680,7688) init tables
#define PREP_PACK   2048
#define PREP_CONVH  (PREP_PACK + 2048)
#define PREP_CONVR  (PREP_CONVH + 512)
#define PREP_TRANS  (PREP_CONVR + 3072)
#define PREP_TOTAL  (PREP_TRANS + 8)

__global__ __launch_bounds__(256) void prep_all(
    const int* __restrict__ mask, const float* __restrict__ hidden,
    const float* __restrict__ rel,
    const float* __restrict__ W0, const float* __restrict__ W1,
    const float* __restrict__ W2) {
    int blk = blockIdx.x;
    int tid = threadIdx.x;

    if (blk < PREP_PACK) {
        // int4 mask pack: thread handles 4 elements; 8 lanes -> one 32-bit word
        int idx = blk * 256 + tid;               // int4 index
        int4 v = ((const int4*)mask)[idx];
        unsigned nib = (v.x != 0 ? 1u : 0u) | (v.y != 0 ? 2u : 0u)
                     | (v.z != 0 ? 4u : 0u) | (v.w != 0 ? 8u : 0u);
        unsigned word = nib << (4 * (tid & 7));
        word |= __shfl_xor_sync(0xffffffffu, word, 1);
        word |= __shfl_xor_sync(0xffffffffu, word, 2);
        word |= __shfl_xor_sync(0xffffffffu, word, 4);
        if ((tid & 7) == 0) g_pmask[idx >> 3] = word;
    } else if (blk < PREP_CONVH) {
        int i = (blk - PREP_PACK) * 256 + tid;
        float4 v = ((const float4*)hidden)[i];
        ((__half2*)g_Hh)[2 * i]     = __floats2half2_rn(v.x, v.y);
        ((__half2*)g_Hh)[2 * i + 1] = __floats2half2_rn(v.z, v.w);
    } else if (blk < PREP_CONVR) {
        int i = (blk - PREP_CONVH) * 256 + tid;
        float4 v = ((const float4*)rel)[i];
        ((__half2*)g_Rh)[2 * i]     = __floats2half2_rn(v.x, v.y);
        ((__half2*)g_Rh)[2 * i + 1] = __floats2half2_rn(v.z, v.w);
    } else if (blk < PREP_TRANS) {
        __shared__ float t[32][33];
        int r = blk - PREP_CONVR;
        int bx = r & 31, by = (r >> 5) & 31, bz = r >> 10;
        const float* W = (bz == 0) ? W0 : (bz == 1) ? W1 : W2;
        __half* D = g_WT + (size_t)bz * DMODEL * DMODEL;
        int tx = tid & 31, ty = tid >> 5;
        int x = bx * 32 + tx;
        int y0 = by * 32 + ty;
        #pragma unroll
        for (int i = 0; i < 32; i += 8)
            t[ty + i][tx] = W[(size_t)(y0 + i) * 1024 + x];
        __syncthreads();
        int nx = by * 32 + tx;
        int ny = bx * 32 + ty;
        #pragma unroll
        for (int i = 0; i < 32; i += 8)
            D[(size_t)(ny + i) * 1024 + nx] = __float2half(t[tx][ty + i]);
    } else {
        int t = (blk - PREP_TRANS) * 256 + tid;
        if (t < 2047) {
            int delta = t - 1023;
            int bC = log_bucket(delta);
            int bP = log_bucket(-delta);
            ushort2 v;
            v.x = (unsigned short)min(max(bC + 256, 0), 511);
            v.y = (unsigned short)min(max(-bP + 256, 0), 511);
            g_idx2s[t] = v;
        }
    }
}

// ================= FP16 GEMM: projections (cp.async double-buffered) =========
#define PAS 40
#define PBUF (128 * PAS)

__global__ __launch_bounds__(256) void gemm_proj_f16(
    const float* __restrict__ bq, const float* __restrict__ bk, const float* __restrict__ bv) {

    int z = blockIdx.z;
    int y = blockIdx.y;
    const __half* A;
    __half* Ch = nullptr;
    bool isV = false;
    int m0;
    if (y < 16) {
        A = g_Hh; m0 = y * 128;
        if (z == 0) Ch = g_Q; else if (z == 1) Ch = g_K; else isV = true;
    } else {
        if (z == 2) return;
        A = g_Rh; m0 = (y - 16) * 128;
        Ch = (z == 0) ? g_PQ : g_PK;
    }
    const __half* WT = g_WT + (size_t)z * DMODEL * DMODEL;
    const float* bias = (z == 0) ? bq : (z == 1) ? bk : bv;
    float outscale = (z == 0) ? (INV_SCALE * LOG2E) : 1.0f;

    extern __shared__ __half smh[];
    __half* As = smh;
    __half* Bs = smh + 2 * PBUF;
    uint32_t as_u32 = (uint32_t)__cvta_generic_to_shared(As);
    uint32_t bs_u32 = (uint32_t)__cvta_generic_to_shared(Bs);

    int tid = threadIdx.x;
    int lane = tid & 31, wid = tid >> 5;
    int qd = lane & 3, g = lane >> 2;
    int wm = (wid >> 2) * 64, wn = (wid & 3) * 32;
    int n0 = blockIdx.x * 128;

    float acc[16][4];
    #pragma unroll
    for (int t = 0; t < 16; t++)
        #pragma unroll
        for (int j = 0; j < 4; j++) acc[t][j] = 0.0f;

    #pragma unroll
    for (int i = 0; i < 2; i++) {
        int idx = tid + i * 256;
        int row = idx >> 2, c8 = (idx & 3) * 8;
        cp16(as_u32 + (row * PAS + c8) * 2, &A[(size_t)(m0 + row) * 1024 + c8]);
        cp16(bs_u32 + (row * PAS + c8) * 2, &WT[(size_t)(n0 + row) * 1024 + c8]);
    }
    asm volatile("cp.async.commit_group;");
    asm volatile("cp.async.wait_group 0;");
    __syncthreads();

    int buf = 0;
    for (int c = 0; c < 32; c++) {
        if (c + 1 < 32) {
            int kk = (c + 1) * 32;
            int nb = buf ^ 1;
            #pragma unroll
            for (int i = 0; i < 2; i++) {
                int idx = tid + i * 256;
                int row = idx >> 2, c8 = (idx & 3) * 8;
                cp16(as_u32 + (nb * PBUF + row * PAS + c8) * 2,
                     &A[(size_t)(m0 + row) * 1024 + kk + c8]);
                cp16(bs_u32 + (nb * PBUF + row * PAS + c8) * 2,
                     &WT[(size_t)(n0 + row) * 1024 + kk + c8]);
            }
            asm volatile("cp.async.commit_group;");
        }

        const __half* Ab = &As[buf * PBUF];
        const __half* Bb = &Bs[buf * PBUF];
        #pragma unroll
        for (int ks = 0; ks < 2; ks++) {
            int kb = ks * 16 + 2 * qd;
            uint32_t af[4][4], bf[4][2];
            #pragma unroll
            for (int i = 0; i < 4; i++) {
                int r = wm + i * 16 + g;
                af[i][0] = *(const uint32_t*)&Ab[r * PAS + kb];
                af[i][1] = *(const uint32_t*)&Ab[(r + 8) * PAS + kb];
                af[i][2] = *(const uint32_t*)&Ab[r * PAS + kb + 8];
                af[i][3] = *(const uint32_t*)&Ab[(r + 8) * PAS + kb + 8];
            }
            #pragma unroll
            for (int j = 0; j < 4; j++) {
                int n = wn + j * 8 + g;
                bf[j][0] = *(const uint32_t*)&Bb[n * PAS + kb];
                bf[j][1] = *(const uint32_t*)&Bb[n * PAS + kb + 8];
            }
            #pragma unroll
            for (int i = 0; i < 4; i++)
                #pragma unroll
                for (int j = 0; j < 4; j++)
                    mma_f16(acc[i * 4 + j], af[i], bf[j]);
        }

        asm volatile("cp.async.wait_group 0;");
        __syncthreads();
        buf ^= 1;
    }

    #pragma unroll
    for (int i = 0; i < 4; i++) {
        #pragma unroll
        for (int j = 0; j < 4; j++) {
            int r = m0 + wm + i * 16 + g;
            int c = n0 + wn + j * 8 + 2 * qd;
            float bx = bias[c], by = bias[c + 1];
            float v00 = (acc[i * 4 + j][0] + bx) * outscale, v01 = (acc[i * 4 + j][1] + by) * outscale;
            float v10 = (acc[i * 4 + j][2] + bx) * outscale, v11 = (acc[i * 4 + j][3] + by) * outscale;
            if (!isV) {
                *(__half2*)&Ch[(size_t)r * 1024 + c] = __floats2half2_rn(v00, v01);
                *(__half2*)&Ch[(size_t)(r + 8) * 1024 + c] = __floats2half2_rn(v10, v11);
            } else {
                int bb = r >> 10, s = r & 1023;
                size_t base = ((size_t)(bb * 1024 + c)) * 1024;
                g_VT[base + s] = __float2half(v00);
                g_VT[base + 1024 + s] = __float2half(v01);
                g_VT[base + s + 8] = __float2half(v10);
                g_VT[base + 1024 + s + 8] = __float2half(v11);
            }
        }
    }
}

// ============ FP16 positional GEMMs: BOTH outputs bucket-major ===============
#define ABH 72

__global__ __launch_bounds__(256) void gemm_abT_f16() {
    int z = blockIdx.z;
    int h = z & 15;
    bool c2p = (z < 16);
    const __half* Ap = c2p ? g_PK : g_PQ;
    const __half* Bp = c2p ? g_Q  : g_K;
    __half* Cp = c2p ? g_c2pT : g_p2cT;
    int r0 = blockIdx.x * 128;
    int n0 = blockIdx.y * 128;

    extern __shared__ __half smh[];
    __half* As = smh;
    __half* Bs = smh + 128 * ABH;

    int tid = threadIdx.x;
    int lane = tid & 31, wid = tid >> 5;
    int qd = lane & 3, g = lane >> 2;
    int wm = (wid >> 1) * 32, wn = (wid & 1) * 64;

    #pragma unroll
    for (int it = 0; it < 8; it++) {
        int idx = tid + it * 256;
        int row = idx >> 4, q = (idx & 15) * 4;
        *(uint2*)&As[row * ABH + q] = *(const uint2*)&Ap[(size_t)(r0 + row) * 1024 + h * 64 + q];
        *(uint2*)&Bs[row * ABH + q] = *(const uint2*)&Bp[(size_t)(n0 + row) * 1024 + h * 64 + q];
    }
    __syncthreads();

    float acc[16][4];
    #pragma unroll
    for (int t = 0; t < 16; t++)
        #pragma unroll
        for (int j = 0; j < 4; j++) acc[t][j] = 0.0f;

    #pragma unroll
    for (int s = 0; s < 4; s++) {
        int kb = s * 16 + 2 * qd;
        uint32_t af[2][4], bf[8][2];
        #pragma unroll
        for (int i = 0; i < 2; i++) {
            int r = wm + i * 16 + g;
            af[i][0] = *(uint32_t*)&As[r * ABH + kb];
            af[i][1] = *(uint32_t*)&As[(r + 8) * ABH + kb];
            af[i][2] = *(uint32_t*)&As[r * ABH + kb + 8];
            af[i][3] = *(uint32_t*)&As[(r + 8) * ABH + kb + 8];
        }
        #pragma unroll
        for (int j = 0; j < 8; j++) {
            int p = wn + j * 8 + g;
            bf[j][0] = *(uint32_t*)&Bs[p * ABH + kb];
            bf[j][1] = *(uint32_t*)&Bs[p * ABH + kb + 8];
        }
        #pragma unroll
        for (int i = 0; i < 2; i++)
            #pragma unroll
            for (int j = 0; j < 8; j++)
                mma_f16(acc[i * 8 + j], af[i], bf[j]);
    }

    #pragma unroll
    for (int i = 0; i < 2; i++) {
        #pragma unroll
        for (int j = 0; j < 8; j++) {
            int r = r0 + wm + i * 16 + g;
            int c = n0 + wn + j * 8 + 2 * qd;
            *(__half2*)&Cp[((size_t)h * POS2 + r) * GTOT + c] =
                __floats2half2_rn(acc[i * 8 + j][0], acc[i * 8 + j][1]);
            *(__half2*)&Cp[((size_t)h * POS2 + r + 8) * GTOT + c] =
                __floats2half2_rn(acc[i * 8 + j][2], acc[i * 8 + j][3]);
        }
    }
}

// ================= FP16 flash attention (cp.async double-buffered) ===========
#define AQH 72
#define KVB (64 * AQH)

__global__ __launch_bounds__(256, 2) void attn_tc_kernel(float* __restrict__ out) {
    extern __shared__ __half smh[];
    __half* Qs = smh;               // [128][72]
    __half* Kb = Qs + 128 * AQH;    // [2][64][72]
    __half* Vb = Kb + 2 * KVB;      // [2][64][72]
    ushort2* idxs = (ushort2*)(Vb + 2 * KVB);  // [1151]

    uint32_t smem_u32 = (uint32_t)__cvta_generic_to_shared(smh);
    uint32_t kb_u32 = smem_u32 + 128 * AQH * 2;
    uint32_t vb_u32 = kb_u32 + 2 * KVB * 2;

    int tid = threadIdx.x;
    int lane = tid & 31, wid = tid >> 5;
    int qd = lane & 3, g = lane >> 2;
    int bh = blockIdx.y;
    int b = bh >> 4, h = bh & 15;
    int q0 = blockIdx.x * 128;

    {
        #pragma unroll
        for (int it = 0; it < 2; it++) {
            int idx = tid + it * 256;
            int row = idx >> 3, c8 = (idx & 7) * 8;
            cp16(kb_u32 + (row * AQH + c8) * 2,
                 &g_K[(size_t)(b * SEQ + row) * 1024 + h * 64 + c8]);
            cp16(vb_u32 + (row * AQH + c8) * 2,
                 &g_VT[((size_t)(b * 1024 + h * 64 + row)) * 1024 + c8]);
        }
        asm volatile("cp.async.commit_group;");
    }
    #pragma unroll
    for (int it = 0; it < 8; it++) {
        int idx = tid + it * 256;
        int row = idx >> 4, q = (idx & 15) * 4;
        *(uint2*)&Qs[row * AQH + q] = *(const uint2*)&g_Q[(size_t)(b * SEQ + q0 + row) * 1024 + h * 64 + q];
    }
    for (int t = tid; t < 1151; t += 256) idxs[t] = g_idx2s[q0 + t];

    int r0l = wid * 16 + g;
    int row0 = q0 + r0l, row1 = row0 + 8;
    int brow0 = b * SEQ + row0;
    const __half* c2pb = &g_c2pT[(size_t)h * POS2 * GTOT];
    const __half* p2cb = &g_p2cT[(size_t)h * POS2 * GTOT + b * SEQ];
    const unsigned* pm0 = &g_pmask[(size_t)(b * SEQ + row0) * 32];
    const unsigned* pm1 = &g_pmask[(size_t)(b * SEQ + row1) * 32];

    float m_run0 = -FLT_MAX, m_run1 = -FLT_MAX, l_run0 = 0.0f, l_run1 = 0.0f;
    float O[8][4];
    #pragma unroll
    for (int f = 0; f < 8; f++)
        #pragma unroll
        for (int j = 0; j < 4; j++) O[f][j] = 0.0f;

    asm volatile("cp.async.wait_group 0;");
    __syncthreads();

    int buf = 0;
    for (int k0 = 0; k0 < SEQ; k0 += 64) {
        if (k0 + 64 < SEQ) {
            int nb = buf ^ 1;
            int nk = k0 + 64;
            #pragma unroll
            for (int it = 0; it < 2; it++) {
                int idx = tid + it * 256;
                int row = idx >> 3, c8 = (idx & 7) * 8;
                cp16(kb_u32 + (nb * KVB + row * AQH + c8) * 2,
                     &g_K[(size_t)(b * SEQ + nk + row) * 1024 + h * 64 + c8]);
                cp16(vb_u32 + (nb * KVB + row * AQH + c8) * 2,
                     &g_VT[((size_t)(b * 1024 + h * 64 + row)) * 1024 + nk + c8]);
            }
            asm volatile("cp.async.commit_group;");
        }

        const __half* Ks = Kb + buf * KVB;
        const __half* Vt = Vb + buf * KVB;

        float sa[8][4];
        #pragma unroll
        for (int f = 0; f < 8; f++)
            #pragma unroll
            for (int j = 0; j < 4; j++) sa[f][j] = 0.0f;

        #pragma unroll
        for (int s = 0; s < 4; s++) {
            int kb = s * 16 + 2 * qd;
            uint32_t a[4];
            a[0] = *(uint32_t*)&Qs[r0l * AQH + kb];
            a[1] = *(uint32_t*)&Qs[(r0l + 8) * AQH + kb];
            a[2] = *(uint32_t*)&Qs[r0l * AQH + kb + 8];
            a[3] = *(uint32_t*)&Qs[(r0l + 8) * AQH + kb + 8];
            #pragma unroll
            for (int nf = 0; nf < 8; nf++) {
                int n = nf * 8 + g;
                uint32_t bfr[2];
                bfr[0] = *(uint32_t*)&Ks[n * AQH + kb];
                bfr[1] = *(uint32_t*)&Ks[n * AQH + kb + 8];
                mma_f16(sa[nf], a, bfr);
            }
        }

        unsigned m0a = pm0[k0 >> 5], m0b = pm0[(k0 >> 5) + 1];
        unsigned m1a = pm1[k0 >> 5], m1b = pm1[(k0 >> 5) + 1];

        float s0max = -FLT_MAX, s1max = -FLT_MAX;
        #pragma unroll
        for (int nf = 0; nf < 8; nf++) {
            #pragma unroll
            for (int j = 0; j < 2; j++) {
                int kl = nf * 8 + 2 * qd + j;
                int kg = k0 + kl;
                int li = r0l - kg + 1023;
                ushort2 i0 = idxs[li];
                ushort2 i1 = idxs[li + 8];
                float b0 = __half2float(__ldg(&c2pb[(size_t)i0.x * GTOT + brow0]))
                         + __half2float(__ldg(&p2cb[(size_t)i0.y * GTOT + kg]));
                float b1 = __half2float(__ldg(&c2pb[(size_t)i1.x * GTOT + brow0 + 8]))
                         + __half2float(__ldg(&p2cb[(size_t)i1.y * GTOT + kg]));
                float v0 = sa[nf][j] + b0;
                float v1 = sa[nf][j + 2] + b1;
                unsigned w0 = (kl & 32) ? m0b : m0a;
                unsigned w1 = (kl & 32) ? m1b : m1a;
                v0 = ((w0 >> (kl & 31)) & 1u) ? v0 : -FLT_MAX;
                v1 = ((w1 >> (kl & 31)) & 1u) ? v1 : -FLT_MAX;
                sa[nf][j] = v0; sa[nf][j + 2] = v1;
                s0max = fmaxf(s0max, v0); s1max = fmaxf(s1max, v1);
            }
        }

        s0max = fmaxf(s0max, __shfl_xor_sync(0xffffffffu, s0max, 1));
        s0max = fmaxf(s0max, __shfl_xor_sync(0xffffffffu, s0max, 2));
        s1max = fmaxf(s1max, __shfl_xor_sync(0xffffffffu, s1max, 1));
        s1max = fmaxf(s1max, __shfl_xor_sync(0xffffffffu, s1max, 2));
        float m0n = fmaxf(m_run0, s0max), m1n = fmaxf(m_run1, s1max);
        float a0 = fexp2(m_run0 - m0n), a1 = fexp2(m_run1 - m1n);
        float psum0 = 0.0f, psum1 = 0.0f;
        #pragma unroll
        for (int nf = 0; nf < 8; nf++) {
            sa[nf][0] = fexp2(sa[nf][0] - m0n);
            sa[nf][1] = fexp2(sa[nf][1] - m0n);
            sa[nf][2] = fexp2(sa[nf][2] - m1n);
            sa[nf][3] = fexp2(sa[nf][3] - m1n);
            psum0 += sa[nf][0] + sa[nf][1];
            psum1 += sa[nf][2] + sa[nf][3];
        }
        psum0 += __shfl_xor_sync(0xffffffffu, psum0, 1);
        psum0 += __shfl_xor_sync(0xffffffffu, psum0, 2);
        psum1 += __shfl_xor_sync(0xffffffffu, psum1, 1);
        psum1 += __shfl_xor_sync(0xffffffffu, psum1, 2);
        l_run0 = l_run0 * a0 + psum0;
        l_run1 = l_run1 * a1 + psum1;
        m_run0 = m0n; m_run1 = m1n;
        #pragma unroll
        for (int f = 0; f < 8; f++) {
            O[f][0] *= a0; O[f][1] *= a0; O[f][2] *= a1; O[f][3] *= a1;
        }

        #pragma unroll
        for (int s = 0; s < 4; s++) {
            uint32_t a[4];
            a[0] = packh2(sa[2 * s][0],     sa[2 * s][1]);
            a[1] = packh2(sa[2 * s][2],     sa[2 * s][3]);
            a[2] = packh2(sa[2 * s + 1][0], sa[2 * s + 1][1]);
            a[3] = packh2(sa[2 * s + 1][2], sa[2 * s + 1][3]);
            int kb = s * 16 + 2 * qd;
            #pragma unroll
            for (int nf = 0; nf < 8; nf++) {
                int n = nf * 8 + g;
                uint32_t bfr[2];
                bfr[0] = *(uint32_t*)&Vt[n * AQH + kb];
                bfr[1] = *(uint32_t*)&Vt[n * AQH + kb + 8];
                mma_f16(O[nf], a, bfr);
            }
        }

        asm volatile("cp.async.wait_group 0;");
        __syncthreads();
        buf ^= 1;
    }

    float invl0 = (m_run0 == -FLT_MAX) ? 0.0f : (1.0f / l_run0);
    float invl1 = (m_run1 == -FLT_MAX) ? 0.0f : (1.0f / l_run1);
    #pragma unroll
    for (int nf = 0; nf < 8; nf++) {
        int d = nf * 8 + 2 * qd;
        float2 o0 = {O[nf][0] * invl0, O[nf][1] * invl0};
        *(float2*)&out[(size_t)(b * SEQ + row0) * 1024 + h * 64 + d] = o0;
        float2 o1 = {O[nf][2] * invl1, O[nf][3] * invl1};
        *(float2*)&out[(size_t)(b * SEQ + row1) * 1024 + h * 64 + d] = o1;
    }
}

// ---------------- launch ----------------------------------------------------
extern "C" void kernel_launch(void* const* d_in, const int* in_sizes, int n_in,
                              void* d_out, int out_size) {
    const float* hidden = (const float*)d_in[0];
    const int*   mask   = (const int*)d_in[1];
    const float* rel    = (const float*)d_in[2];
    const float* Wq     = (const float*)d_in[3];
    const float* bq     = (const float*)d_in[4];
    const float* Wk     = (const float*)d_in[5];
    const float* bk     = (const float*)d_in[6];
    const float* Wv     = (const float*)d_in[7];
    const float* bv     = (const float*)d_in[8];
    float* out = (float*)d_out;

    prep_all<<<PREP_TOTAL, 256>>>(mask, hidden, rel, Wq, Wk, Wv);

    int smem_proj = 4 * PBUF * (int)sizeof(__half);
    cudaFuncSetAttribute(gemm_proj_f16, cudaFuncAttributeMaxDynamicSharedMemorySize, smem_proj);
    gemm_proj_f16<<<dim3(8, 20, 3), 256, smem_proj>>>(bq, bk, bv);

    int smem_abt = (2 * 128 * ABH) * (int)sizeof(__half);
    cudaFuncSetAttribute(gemm_abT_f16, cudaFuncAttributeMaxDynamicSharedMemorySize, smem_abt);
    gemm_abT_f16<<<dim3(POS2 / 128, GTOT / 128, 32), 256, smem_abt>>>();

    int smem_attn = (128 * AQH + 4 * KVB) * (int)sizeof(__half) + 1152 * (int)sizeof(ushort2);
    cudaFuncSetAttribute(attn_tc_kernel, cudaFuncAttributeMaxDynamicSharedMemorySize, smem_attn);
    attn_tc_kernel<<<dim3(SEQ / 128, NBATCH * NHEAD), 256, smem_attn>>>(out);
}